// round 3
// baseline (speedup 1.0000x reference)
#include <cuda_runtime.h>
#include <math.h>
#include <float.h>

// Problem constants
#define Bc    2
#define Hh    64
#define Ww    160
#define DIMc  256
#define NHc   8
#define HDc   32
#define Nn    (Hh * Ww)       // 10240 tokens per batch
#define Mrows (Bc * Nn)       // 20480 total rows
#define SCALEF 0.17677669529663687f   // 32^-0.5

// Static scratch
__device__ float g_q[Mrows * DIMc];
__device__ float g_k[Mrows * DIMc];
__device__ float g_v[Mrows * DIMc];
__device__ float g_h[Mrows * DIMc];

// ---------------------------------------------------------------------------
// tf32 helpers
// ---------------------------------------------------------------------------
__device__ __forceinline__ unsigned f2tf32(float v) {
    unsigned r;
    asm("cvt.rna.tf32.f32 %0, %1;" : "=r"(r) : "f"(v));
    return r;
}

__device__ __forceinline__ void mma1688(float c[4], const unsigned a[4], const unsigned b[2]) {
    asm volatile(
        "mma.sync.aligned.m16n8k8.row.col.f32.tf32.tf32.f32 "
        "{%0,%1,%2,%3},{%4,%5,%6,%7},{%8,%9},{%0,%1,%2,%3};"
        : "+f"(c[0]), "+f"(c[1]), "+f"(c[2]), "+f"(c[3])
        : "r"(a[0]), "r"(a[1]), "r"(a[2]), "r"(a[3]), "r"(b[0]), "r"(b[1]));
}

// ---------------------------------------------------------------------------
// 3xTF32 tensor-core GEMM with pre-split hi/lo staged in smem as uint2.
// C[M x 256] = A[M x 256] @ W[256 x 256]
// BM=128, BN=128, BK=16, 512 threads (16 warps, warp tile 32x32).
// Smem: As uint2 [2][16][140] (k-major, XOR-swizzled m), Bs uint2 [2][16][132].
// ---------------------------------------------------------------------------
#define KDIM 256
#define AS2 140                      // uint2 per A k-row (128 m + 12 pad)
#define BS2 132                      // uint2 per B k-row (128 n + 4 pad)
#define ASZ (16 * AS2)               // 2240 uint2 per buffer
#define BSZ (16 * BS2)               // 2112 uint2 per buffer
#define SMEM_BYTES ((2 * ASZ + 2 * BSZ) * 8)   // 69632

__device__ __forceinline__ void tc_gemm_body(const float* __restrict__ A,
                                             const float* __restrict__ W,
                                             float* __restrict__ C) {
    extern __shared__ uint2 sm2[];
    uint2* As = sm2;               // [2][16][AS2]
    uint2* Bs = sm2 + 2 * ASZ;     // [2][16][BS2]

    const int t    = threadIdx.x;
    const int warp = t >> 5;
    const int lane = t & 31;
    const int q    = lane >> 2;   // 0..7
    const int c4   = lane & 3;    // 0..3

    const int bm = blockIdx.y * 128;
    const int bn = blockIdx.x * 128;
    const int wm = (warp >> 2) * 32;
    const int wn = (warp & 3) * 32;

    // --- staging indices ---
    const int am   = t >> 2;            // 0..127 (A row)
    const int akg  = (t & 3) * 4;       // k group 0,4,8,12
    const int akey = (t & 3) << 3;      // swizzle key for this thread's k rows
    const int amx  = am ^ akey;         // swizzled m for A stores
    const int bkr  = t >> 5;            // 0..15 (B k-row)
    const int bcl  = lane;              // B col (+32j)

    const float* Ag = A + (size_t)(bm + am) * KDIM + akg;
    const float* Bg = W + (size_t)bkr * KDIM + bn + bcl;

    float acc[2][4][4];
#pragma unroll
    for (int i = 0; i < 2; i++)
#pragma unroll
        for (int j = 0; j < 4; j++)
#pragma unroll
            for (int e = 0; e < 4; e++) acc[i][j][e] = 0.f;

    // --- prologue: stage tile 0 ---
    float4 a4 = *reinterpret_cast<const float4*>(Ag);
    float b4[4];
#pragma unroll
    for (int j = 0; j < 4; j++) b4[j] = Bg[32 * j];

    {
        const float av[4] = {a4.x, a4.y, a4.z, a4.w};
#pragma unroll
        for (int j = 0; j < 4; j++) {
            unsigned hi = f2tf32(av[j]);
            unsigned lo = f2tf32(av[j] - __uint_as_float(hi));
            As[(akg + j) * AS2 + amx] = make_uint2(hi, lo);
            unsigned bh = f2tf32(b4[j]);
            unsigned bl = f2tf32(b4[j] - __uint_as_float(bh));
            Bs[bkr * BS2 + bcl + 32 * j] = make_uint2(bh, bl);
        }
    }
    __syncthreads();

#pragma unroll 1
    for (int it = 0; it < 16; ++it) {
        const int cur = it & 1;
        if (it < 15) {
            a4 = *reinterpret_cast<const float4*>(Ag + (it + 1) * 16);
#pragma unroll
            for (int j = 0; j < 4; j++)
                b4[j] = Bg[(size_t)(it + 1) * 16 * KDIM + 32 * j];
        }

        const uint2* Ac = As + cur * ASZ;
        const uint2* Bcs = Bs + cur * BSZ;

#pragma unroll
        for (int ks = 0; ks < 16; ks += 8) {
            const int S0 = ((ks >> 2) & 3) << 3;        // swizzle for rows ks+c4
            const int S1 = (((ks + 4) >> 2) & 3) << 3;  // swizzle for rows ks+c4+4

            unsigned ahi[2][4], alo[2][4];
#pragma unroll
            for (int i = 0; i < 2; i++) {
                const int mbq = wm + i * 16 + q;
                uint2 a0 = Ac[(ks + c4) * AS2 + ((mbq)     ^ S0)];
                uint2 a1 = Ac[(ks + c4) * AS2 + ((mbq + 8) ^ S0)];
                uint2 a2 = Ac[(ks + c4 + 4) * AS2 + ((mbq)     ^ S1)];
                uint2 a3 = Ac[(ks + c4 + 4) * AS2 + ((mbq + 8) ^ S1)];
                ahi[i][0] = a0.x; alo[i][0] = a0.y;
                ahi[i][1] = a1.x; alo[i][1] = a1.y;
                ahi[i][2] = a2.x; alo[i][2] = a2.y;
                ahi[i][3] = a3.x; alo[i][3] = a3.y;
            }
            unsigned bhi[4][2], blo[4][2];
#pragma unroll
            for (int j = 0; j < 4; j++) {
                const int nb = wn + j * 8 + q;
                uint2 w0 = Bcs[(ks + c4) * BS2 + nb];
                uint2 w1 = Bcs[(ks + c4 + 4) * BS2 + nb];
                bhi[j][0] = w0.x; blo[j][0] = w0.y;
                bhi[j][1] = w1.x; blo[j][1] = w1.y;
            }
#pragma unroll
            for (int i = 0; i < 2; i++)
#pragma unroll
                for (int j = 0; j < 4; j++) {
                    mma1688(acc[i][j], ahi[i], blo[j]);
                    mma1688(acc[i][j], alo[i], bhi[j]);
                    mma1688(acc[i][j], ahi[i], bhi[j]);
                }
        }

        if (it < 15) {
            uint2* An = As + (cur ^ 1) * ASZ;
            uint2* Bn = Bs + (cur ^ 1) * BSZ;
            const float av[4] = {a4.x, a4.y, a4.z, a4.w};
#pragma unroll
            for (int j = 0; j < 4; j++) {
                unsigned hi = f2tf32(av[j]);
                unsigned lo = f2tf32(av[j] - __uint_as_float(hi));
                An[(akg + j) * AS2 + amx] = make_uint2(hi, lo);
                unsigned bh = f2tf32(b4[j]);
                unsigned bl = f2tf32(b4[j] - __uint_as_float(bh));
                Bn[bkr * BS2 + bcl + 32 * j] = make_uint2(bh, bl);
            }
            __syncthreads();
        }
    }

    // --- epilogue ---
#pragma unroll
    for (int i = 0; i < 2; i++) {
#pragma unroll
        for (int j = 0; j < 4; j++) {
            const int gr0 = bm + wm + i * 16 + q;
            const int gc  = bn + wn + j * 8 + 2 * c4;
            *reinterpret_cast<float2*>(C + (size_t)gr0 * KDIM + gc) =
                make_float2(acc[i][j][0], acc[i][j][1]);
            *reinterpret_cast<float2*>(C + (size_t)(gr0 + 8) * KDIM + gc) =
                make_float2(acc[i][j][2], acc[i][j][3]);
        }
    }
}

__global__ void __launch_bounds__(512, 1)
gemm_qkv(const float* __restrict__ X,
         const float* __restrict__ Wq, const float* __restrict__ Wk,
         const float* __restrict__ Wv) {
    const float* W = (blockIdx.z == 0) ? Wq : (blockIdx.z == 1) ? Wk : Wv;
    float* C = (blockIdx.z == 0) ? g_q : (blockIdx.z == 1) ? g_k : g_v;
    tc_gemm_body(X, W, C);
}

__global__ void __launch_bounds__(512, 1)
gemm_proj(const float* __restrict__ W, float* __restrict__ out) {
    tc_gemm_body(g_h, W, out);
}

// ---------------------------------------------------------------------------
// Attention: one block per token (8 warps = 8 heads), lane = dim.
// V gather deferred until after scores to cut register pressure.
// ---------------------------------------------------------------------------
__global__ void __launch_bounds__(256, 6)
attn_kernel(const float* __restrict__ mo) {
    const int r = blockIdx.x;
    const int b = r / Nn;
    const int warp = threadIdx.x >> 5;
    const int lane = threadIdx.x & 31;

    float ox = mo[(size_t)r * 2 + 0];
    float oy = mo[(size_t)r * 2 + 1];
    ox = fminf(fmaxf(ox, 1.0f), (float)(Ww - 2) - 0.001f);
    oy = fminf(fmaxf(oy, 1.0f), (float)(Hh - 2) - 0.001f);
    const float mx = floorf(ox), my = floorf(oy);
    const float fx = ox - mx,   fy = oy - my;

    const int a   = lane & 15;
    const int axp = a & 3;
    const int ayp = a >> 2;
    const int ix = (int)mx + axp - 1;
    const int iy = (int)my + ayp - 1;
    const int idx_a = iy * Ww + ix;
    const float wxv = (axp == 0) ? (1.f - fx) : ((axp == 3) ? fx : 1.f);
    const float wyv = (ayp == 0) ? (1.f - fy) : ((ayp == 3) ? fy : 1.f);
    const float bw = wxv * wyv;

    const size_t head_off = (size_t)warp * HDc + lane;
    const float qd = g_q[(size_t)r * DIMc + head_off] * SCALEF;
    const int base_b = b * Nn;

    // K gather
    float kv[16];
#pragma unroll
    for (int aa = 0; aa < 16; aa++) {
        int ia = __shfl_sync(0xffffffffu, idx_a, aa);
        kv[aa] = g_k[(size_t)(base_b + ia) * DIMc + head_off];
    }

    // scores
    float attn_mine = -FLT_MAX;
#pragma unroll
    for (int aa = 0; aa < 16; aa++) {
        float s = qd * kv[aa];
#pragma unroll
        for (int o = 16; o > 0; o >>= 1) s += __shfl_xor_sync(0xffffffffu, s, o);
        if (lane == aa) attn_mine = s;
    }

    // V gather (overlaps softmax below)
    float vv[16];
#pragma unroll
    for (int aa = 0; aa < 16; aa++) {
        int ia = __shfl_sync(0xffffffffu, idx_a, aa);
        vv[aa] = g_v[(size_t)(base_b + ia) * DIMc + head_off];
    }

    // bilinear-weighted stable softmax (lanes 0..15 hold scores)
    float m = attn_mine;
#pragma unroll
    for (int o = 8; o > 0; o >>= 1) m = fmaxf(m, __shfl_xor_sync(0xffffffffu, m, o));
    float e = (lane < 16) ? __expf(attn_mine - m) * bw : 0.f;
    float se = e;
#pragma unroll
    for (int o = 8; o > 0; o >>= 1) se += __shfl_xor_sync(0xffffffffu, se, o);
    const float p = __fdividef(e, se);

    float accv = 0.f;
#pragma unroll
    for (int aa = 0; aa < 16; aa++) {
        float pa = __shfl_sync(0xffffffffu, p, aa);
        accv += pa * vv[aa];
    }
    g_h[(size_t)r * DIMc + head_off] = accv;
}

// ---------------------------------------------------------------------------
extern "C" void kernel_launch(void* const* d_in, const int* in_sizes, int n_in,
                              void* d_out, int out_size) {
    const float* x  = (const float*)d_in[0];
    const float* mo = (const float*)d_in[1];
    const float* Wq = (const float*)d_in[2];
    const float* Wk = (const float*)d_in[3];
    const float* Wv = (const float*)d_in[4];
    const float* Wp = (const float*)d_in[5];
    float* out = (float*)d_out;

    cudaFuncSetAttribute(gemm_qkv, cudaFuncAttributeMaxDynamicSharedMemorySize, SMEM_BYTES);
    cudaFuncSetAttribute(gemm_proj, cudaFuncAttributeMaxDynamicSharedMemorySize, SMEM_BYTES);

    dim3 gqkv(256 / 128, Mrows / 128, 3);   // (2, 160, 3)
    gemm_qkv<<<gqkv, 512, SMEM_BYTES>>>(x, Wq, Wk, Wv);
    attn_kernel<<<Mrows, 256>>>(mo);
    dim3 gp(256 / 128, Mrows / 128);        // (2, 160)
    gemm_proj<<<gp, 512, SMEM_BYTES>>>(Wp, out);
}

// round 6
// speedup vs baseline: 1.6921x; 1.6921x over previous
#include <cstdint>
#include <cuda_runtime.h>
#include <cuda_bf16.h>
#include <math.h>
#include <float.h>

// Problem constants
#define Bc    2
#define Hh    64
#define Ww    160
#define DIMc  256
#define NHc   8
#define HDc   32
#define Nn    (Hh * Ww)       // 10240 tokens per batch
#define Mrows (Bc * Nn)       // 20480 total rows
#define SCALEF 0.17677669529663687f   // 32^-0.5

// Static scratch
__device__ float g_q[Mrows * DIMc];
__device__ float g_k[Mrows * DIMc];
__device__ float g_v[Mrows * DIMc];
__device__ float g_h[Mrows * DIMc];

// ---------------------------------------------------------------------------
// helpers
// ---------------------------------------------------------------------------
__device__ __forceinline__ uint32_t smem_to_u32(const void* smem_ptr) {
    uint32_t addr;
    asm("{ .reg .u64 tmp; cvta.to.shared.u64 tmp, %1; cvt.u32.u64 %0, tmp; }"
        : "=r"(addr) : "l"(smem_ptr));
    return addr;
}

// bf16 hi/lo split: h = packed {lo half: bf16(x), hi half: bf16(y)}, l = residues
__device__ __forceinline__ void bsplit(float x, float y, uint32_t& h, uint32_t& l) {
    asm("cvt.rn.bf16x2.f32 %0, %1, %2;" : "=r"(h) : "f"(y), "f"(x));
    float hx = __uint_as_float(h << 16);
    float hy = __uint_as_float(h & 0xffff0000u);
    asm("cvt.rn.bf16x2.f32 %0, %1, %2;" : "=r"(l) : "f"(y - hy), "f"(x - hx));
}

__device__ __forceinline__ void mma_bf16(float* c, const uint32_t* a,
                                         uint32_t b0, uint32_t b1) {
    asm volatile(
        "mma.sync.aligned.m16n8k16.row.col.f32.bf16.bf16.f32 "
        "{%0,%1,%2,%3},{%4,%5,%6,%7},{%8,%9},{%0,%1,%2,%3};"
        : "+f"(c[0]), "+f"(c[1]), "+f"(c[2]), "+f"(c[3])
        : "r"(a[0]), "r"(a[1]), "r"(a[2]), "r"(a[3]), "r"(b0), "r"(b1));
}

__device__ __forceinline__ void ldsm_x4_t(uint32_t* r, uint32_t addr) {
    asm volatile(
        "ldmatrix.sync.aligned.m8n8.x4.trans.shared.b16 {%0,%1,%2,%3}, [%4];"
        : "=r"(r[0]), "=r"(r[1]), "=r"(r[2]), "=r"(r[3]) : "r"(addr));
}

// ---------------------------------------------------------------------------
// bf16x3 GEMM: C[M x 256] = A[M x 256] @ W[256 x 256]
// BM=128, BN=128, BK=32, 512 threads (16 warps, warp tile 32x32), dbl-buffered.
// A smem: interleaved uint2{hi,lo} per bf16-pair, row stride 20 uint2 (160B).
// B smem: hi/lo separate [k][n] bf16, row stride 136 bf16 (272B), ldmatrix.trans.
// ---------------------------------------------------------------------------
#define A_STG   20480            // bytes per A stage (128*20*8)
#define B_STG   8704             // bytes per B stage half (32*136*2)
#define BH_BASE 40960            // 2*A_STG
#define BL_BASE 58368            // BH_BASE + 2*B_STG
#define SMEM_GEMM 75776          // BL_BASE + 2*B_STG

__device__ __forceinline__ void stage_store(char* smem_c, int nxt,
                                            uint32_t a_st, uint32_t b_st,
                                            float4 a0r, float4 a1r,
                                            float4 b0r, float4 b1r) {
    char* An  = smem_c + nxt * A_STG;
    char* BHn = smem_c + BH_BASE + nxt * B_STG;
    char* BLn = smem_c + BL_BASE + nxt * B_STG;
    uint32_t h01, l01, h23, l23;
    bsplit(a0r.x, a0r.y, h01, l01);
    bsplit(a0r.z, a0r.w, h23, l23);
    *reinterpret_cast<uint4*>(An + a_st) = make_uint4(h01, l01, h23, l23);
    bsplit(a1r.x, a1r.y, h01, l01);
    bsplit(a1r.z, a1r.w, h23, l23);
    *reinterpret_cast<uint4*>(An + a_st + 64 * 160) = make_uint4(h01, l01, h23, l23);
    bsplit(b0r.x, b0r.y, h01, l01);
    bsplit(b0r.z, b0r.w, h23, l23);
    *reinterpret_cast<uint2*>(BHn + b_st) = make_uint2(h01, h23);
    *reinterpret_cast<uint2*>(BLn + b_st) = make_uint2(l01, l23);
    bsplit(b1r.x, b1r.y, h01, l01);
    bsplit(b1r.z, b1r.w, h23, l23);
    *reinterpret_cast<uint2*>(BHn + b_st + 16 * 272) = make_uint2(h01, h23);
    *reinterpret_cast<uint2*>(BLn + b_st + 16 * 272) = make_uint2(l01, l23);
}

__device__ __forceinline__ void bf16x3_gemm(const float* __restrict__ A,
                                            const float* __restrict__ W,
                                            float* __restrict__ C) {
    extern __shared__ char smem_c[];
    const uint32_t sb = smem_to_u32(smem_c);
    const int t    = threadIdx.x;
    const int warp = t >> 5;
    const int lane = t & 31;
    const int q    = lane >> 2;
    const int c4   = lane & 3;
    const int bm = blockIdx.y * 128;
    const int bn = blockIdx.x * 128;
    const int wm = (warp >> 2) * 32;
    const int wn = (warp & 3) * 32;

    const float* Ag = A + (size_t)(bm + (t >> 3)) * DIMc + (t & 7) * 4;
    const float* Bg = W + (size_t)(t >> 5) * DIMc + bn + (t & 31) * 4;
    const uint32_t a_st = (uint32_t)((t >> 3) * 160 + (t & 7) * 16);
    const uint32_t b_st = (uint32_t)((t >> 5) * 272 + (t & 31) * 8);

    float acc[2][4][4];
#pragma unroll
    for (int i = 0; i < 2; i++)
#pragma unroll
        for (int j = 0; j < 4; j++)
#pragma unroll
            for (int e = 0; e < 4; e++) acc[i][j][e] = 0.f;

    // prologue: stage 0
    float4 a0r = *reinterpret_cast<const float4*>(Ag);
    float4 a1r = *reinterpret_cast<const float4*>(Ag + 64 * DIMc);
    float4 b0r = *reinterpret_cast<const float4*>(Bg);
    float4 b1r = *reinterpret_cast<const float4*>(Bg + 16 * DIMc);
    stage_store(smem_c, 0, a_st, b_st, a0r, a1r, b0r, b1r);
    __syncthreads();

#pragma unroll 1
    for (int s = 0; s < 8; s++) {
        const int cur = s & 1;
        if (s < 7) {
            const int k0 = (s + 1) * 32;
            a0r = *reinterpret_cast<const float4*>(Ag + k0);
            a1r = *reinterpret_cast<const float4*>(Ag + 64 * DIMc + k0);
            b0r = *reinterpret_cast<const float4*>(Bg + (size_t)k0 * DIMc);
            b1r = *reinterpret_cast<const float4*>(Bg + (size_t)(k0 + 16) * DIMc);
        }

        const char* Ab = smem_c + cur * A_STG;
        const uint32_t bhb = sb + BH_BASE + cur * B_STG;
        const uint32_t blb = sb + BL_BASE + cur * B_STG;

#pragma unroll
        for (int k16 = 0; k16 < 2; k16++) {
            uint32_t ah[2][4], al[2][4];
#pragma unroll
            for (int mt = 0; mt < 2; mt++) {
                const uint2* Ap = reinterpret_cast<const uint2*>(Ab)
                                + (wm + mt * 16 + q) * 20 + k16 * 8 + c4;
                uint2 u0 = Ap[0];
                uint2 u1 = Ap[160];
                uint2 u2 = Ap[4];
                uint2 u3 = Ap[164];
                ah[mt][0] = u0.x; al[mt][0] = u0.y;
                ah[mt][1] = u1.x; al[mt][1] = u1.y;
                ah[mt][2] = u2.x; al[mt][2] = u2.y;
                ah[mt][3] = u3.x; al[mt][3] = u3.y;
            }
            uint32_t bh[2][4], bl[2][4];
#pragma unroll
            for (int nc = 0; nc < 2; nc++) {
                uint32_t off = (uint32_t)((k16 * 16 + (lane & 15)) * 272
                              + (wn + nc * 16 + ((lane >> 4) << 3)) * 2);
                ldsm_x4_t(bh[nc], bhb + off);
                ldsm_x4_t(bl[nc], blb + off);
            }
#pragma unroll
            for (int mt = 0; mt < 2; mt++)
#pragma unroll
                for (int n8 = 0; n8 < 4; n8++) {
                    const int nc = n8 >> 1, jj = (n8 & 1) * 2;
                    mma_bf16(acc[mt][n8], ah[mt], bh[nc][jj], bh[nc][jj + 1]);
                    mma_bf16(acc[mt][n8], ah[mt], bl[nc][jj], bl[nc][jj + 1]);
                    mma_bf16(acc[mt][n8], al[mt], bh[nc][jj], bh[nc][jj + 1]);
                }
        }

        if (s < 7) {
            stage_store(smem_c, cur ^ 1, a_st, b_st, a0r, a1r, b0r, b1r);
            __syncthreads();
        }
    }

    // epilogue
#pragma unroll
    for (int mt = 0; mt < 2; mt++) {
#pragma unroll
        for (int n8 = 0; n8 < 4; n8++) {
            const int gr0 = bm + wm + mt * 16 + q;
            const int gc  = bn + wn + n8 * 8 + 2 * c4;
            *reinterpret_cast<float2*>(C + (size_t)gr0 * DIMc + gc) =
                make_float2(acc[mt][n8][0], acc[mt][n8][1]);
            *reinterpret_cast<float2*>(C + (size_t)(gr0 + 8) * DIMc + gc) =
                make_float2(acc[mt][n8][2], acc[mt][n8][3]);
        }
    }
}

__global__ void __launch_bounds__(512, 1)
gemm_qkv(const float* __restrict__ X,
         const float* __restrict__ Wq, const float* __restrict__ Wk,
         const float* __restrict__ Wv) {
    const float* W = (blockIdx.z == 0) ? Wq : (blockIdx.z == 1) ? Wk : Wv;
    float* C = (blockIdx.z == 0) ? g_q : (blockIdx.z == 1) ? g_k : g_v;
    bf16x3_gemm(X, W, C);
}

__global__ void __launch_bounds__(512, 1)
gemm_proj(const float* __restrict__ W, float* __restrict__ out) {
    bf16x3_gemm(g_h, W, out);
}

// ---------------------------------------------------------------------------
// Attention: block per token, warp per head, lane = dim.
// Shuffle-lean: per-lane index arithmetic + multi-value butterfly reduction.
// ---------------------------------------------------------------------------
__global__ void __launch_bounds__(256, 6)
attn_kernel(const float* __restrict__ mo) {
    const int r = blockIdx.x;
    const int b = (r >= Nn) ? 1 : 0;
    const int warp = threadIdx.x >> 5;
    const int lane = threadIdx.x & 31;

    float ox = mo[(size_t)r * 2 + 0];
    float oy = mo[(size_t)r * 2 + 1];
    ox = fminf(fmaxf(ox, 1.0f), (float)(Ww - 2) - 0.001f);
    oy = fminf(fmaxf(oy, 1.0f), (float)(Hh - 2) - 0.001f);
    const float mx = floorf(ox), my = floorf(oy);
    const float fx = ox - mx,   fy = oy - my;

    const int ibase = b * Nn + ((int)my - 1) * Ww + ((int)mx - 1);

    const size_t head_off = (size_t)warp * HDc + lane;
    const float qd = g_q[(size_t)r * DIMc + head_off] * SCALEF;

    // K gather: position a = 4*dy + dx
    float part[16];
#pragma unroll
    for (int a = 0; a < 16; a++) {
        int ia = ibase + (a >> 2) * Ww + (a & 3);
        part[a] = qd * g_k[(size_t)ia * DIMc + head_off];
    }

    // Multi-value butterfly: 16 dot-products reduced with 16 shuffles.
    // After all steps lane l holds s[a] with a = (l>>1)&15.
    float v8[8];
    {
        const bool hi = (lane & 16) != 0;
#pragma unroll
        for (int j = 0; j < 8; j++) {
            float send = hi ? part[j] : part[j + 8];
            float keep = hi ? part[j + 8] : part[j];
            v8[j] = keep + __shfl_xor_sync(0xffffffffu, send, 16);
        }
    }
    float v4[4];
    {
        const bool hi = (lane & 8) != 0;
#pragma unroll
        for (int j = 0; j < 4; j++) {
            float send = hi ? v8[j] : v8[j + 4];
            float keep = hi ? v8[j + 4] : v8[j];
            v4[j] = keep + __shfl_xor_sync(0xffffffffu, send, 8);
        }
    }
    float v2[2];
    {
        const bool hi = (lane & 4) != 0;
#pragma unroll
        for (int j = 0; j < 2; j++) {
            float send = hi ? v2[0] * 0.f + v4[j] : v4[j + 2];  // placeholder avoided below
            (void)send;
        }
        // (explicit to avoid compiler confusion)
        float s0 = hi ? v4[2] : v4[0];
        float s1 = hi ? v4[3] : v4[1];
        float d0 = hi ? v4[0] : v4[2];
        float d1 = hi ? v4[1] : v4[3];
        v2[0] = s0 + __shfl_xor_sync(0xffffffffu, d0, 4);
        v2[1] = s1 + __shfl_xor_sync(0xffffffffu, d1, 4);
    }
    float v1;
    {
        const bool hi = (lane & 2) != 0;
        float keep = hi ? v2[1] : v2[0];
        float send = hi ? v2[0] : v2[1];
        v1 = keep + __shfl_xor_sync(0xffffffffu, send, 2);
    }
    float sfin = v1 + __shfl_xor_sync(0xffffffffu, v1, 1);

    // regroup: lane gets s[lane&15] from lane 2*(lane&15)
    float sa = __shfl_sync(0xffffffffu, sfin, (lane & 15) * 2);

    // bilinear weight for position a = lane&15
    const int axp = lane & 3;
    const int ayp = (lane >> 2) & 3;
    const float wxv = (axp == 0) ? (1.f - fx) : ((axp == 3) ? fx : 1.f);
    const float wyv = (ayp == 0) ? (1.f - fy) : ((ayp == 3) ? fy : 1.f);
    const float bw = wxv * wyv;

    // softmax over 16 positions
    float mval = sa;
#pragma unroll
    for (int o = 8; o > 0; o >>= 1)
        mval = fmaxf(mval, __shfl_xor_sync(0xffffffffu, mval, o));
    float e = (lane < 16) ? __expf(sa - mval) * bw : 0.f;
    float se = e;
#pragma unroll
    for (int o = 16; o > 0; o >>= 1)
        se += __shfl_xor_sync(0xffffffffu, se, o);
    const float p = __fdividef(e, se);

    // V gather + weighted accumulate
    float accv = 0.f;
#pragma unroll
    for (int a = 0; a < 16; a++) {
        int ia = ibase + (a >> 2) * Ww + (a & 3);
        float va = g_v[(size_t)ia * DIMc + head_off];
        float pa = __shfl_sync(0xffffffffu, p, a);
        accv += pa * va;
    }
    g_h[(size_t)r * DIMc + head_off] = accv;
}

// ---------------------------------------------------------------------------
extern "C" void kernel_launch(void* const* d_in, const int* in_sizes, int n_in,
                              void* d_out, int out_size) {
    const float* x  = (const float*)d_in[0];
    const float* mo = (const float*)d_in[1];
    const float* Wq = (const float*)d_in[2];
    const float* Wk = (const float*)d_in[3];
    const float* Wv = (const float*)d_in[4];
    const float* Wp = (const float*)d_in[5];
    float* out = (float*)d_out;

    cudaFuncSetAttribute(gemm_qkv, cudaFuncAttributeMaxDynamicSharedMemorySize, SMEM_GEMM);
    cudaFuncSetAttribute(gemm_proj, cudaFuncAttributeMaxDynamicSharedMemorySize, SMEM_GEMM);

    dim3 gqkv(2, Mrows / 128, 3);   // (2, 160, 3)
    gemm_qkv<<<gqkv, 512, SMEM_GEMM>>>(x, Wq, Wk, Wv);
    attn_kernel<<<Mrows, 256>>>(mo);
    dim3 gp(2, Mrows / 128);        // (2, 160)
    gemm_proj<<<gp, 512, SMEM_GEMM>>>(Wp, out);
}

// round 7
// speedup vs baseline: 1.8619x; 1.1003x over previous
#include <cstdint>
#include <cuda_runtime.h>
#include <cuda_bf16.h>
#include <math.h>
#include <float.h>

// Problem constants
#define Bc    2
#define Hh    64
#define Ww    160
#define DIMc  256
#define NHc   8
#define HDc   32
#define Nn    (Hh * Ww)       // 10240 tokens per batch
#define Mrows (Bc * Nn)       // 20480 total rows
#define SCALEF 0.17677669529663687f   // 32^-0.5

// Static scratch
__device__ float g_q[Mrows * DIMc];
__device__ float g_k[Mrows * DIMc];
__device__ float g_v[Mrows * DIMc];
__device__ float g_h[Mrows * DIMc];

// ---------------------------------------------------------------------------
// helpers
// ---------------------------------------------------------------------------
__device__ __forceinline__ uint32_t smem_to_u32(const void* smem_ptr) {
    uint32_t addr;
    asm("{ .reg .u64 tmp; cvta.to.shared.u64 tmp, %1; cvt.u32.u64 %0, tmp; }"
        : "=r"(addr) : "l"(smem_ptr));
    return addr;
}

// bf16 hi/lo split: h = packed {lo half: bf16(x), hi half: bf16(y)}, l = residues
__device__ __forceinline__ void bsplit(float x, float y, uint32_t& h, uint32_t& l) {
    asm("cvt.rn.bf16x2.f32 %0, %1, %2;" : "=r"(h) : "f"(y), "f"(x));
    float hx = __uint_as_float(h << 16);
    float hy = __uint_as_float(h & 0xffff0000u);
    asm("cvt.rn.bf16x2.f32 %0, %1, %2;" : "=r"(l) : "f"(y - hy), "f"(x - hx));
}

__device__ __forceinline__ void mma_bf16(float* c, const uint32_t* a,
                                         uint32_t b0, uint32_t b1) {
    asm volatile(
        "mma.sync.aligned.m16n8k16.row.col.f32.bf16.bf16.f32 "
        "{%0,%1,%2,%3},{%4,%5,%6,%7},{%8,%9},{%0,%1,%2,%3};"
        : "+f"(c[0]), "+f"(c[1]), "+f"(c[2]), "+f"(c[3])
        : "r"(a[0]), "r"(a[1]), "r"(a[2]), "r"(a[3]), "r"(b0), "r"(b1));
}

__device__ __forceinline__ void ldsm_x4_t(uint32_t* r, uint32_t addr) {
    asm volatile(
        "ldmatrix.sync.aligned.m8n8.x4.trans.shared.b16 {%0,%1,%2,%3}, [%4];"
        : "=r"(r[0]), "=r"(r[1]), "=r"(r[2]), "=r"(r[3]) : "r"(addr));
}

// ---------------------------------------------------------------------------
// bf16x3 GEMM: C[M x 256] = A[M x 256] @ W[256 x 256]
// BM=64, BN=128, BK=32, 256 threads (8 warps: 2m x 4n, warp tile 32x32),
// double-buffered; sized for 2 CTAs/SM so staging overlaps the other CTA's MMAs.
// A smem: interleaved uint2{hi,lo} per bf16-pair, row stride 160 B.
// B smem: hi/lo separate [k][n] bf16, row stride 272 B, via ldmatrix.trans.
// ---------------------------------------------------------------------------
#define A_STG   10240            // bytes per A stage (64 rows * 160 B)
#define B_STG   8704             // bytes per B stage half (32*272)
#define BH_BASE 20480            // 2*A_STG
#define BL_BASE 37888            // BH_BASE + 2*B_STG
#define SMEM_GEMM 55296          // BL_BASE + 2*B_STG

__device__ __forceinline__ void stage_store(char* smem_c, int nxt,
                                            uint32_t a_st0, uint32_t a_st1,
                                            uint32_t b_st0,
                                            float4 a0r, float4 a1r,
                                            const float4* b4r) {
    char* An  = smem_c + nxt * A_STG;
    char* BHn = smem_c + BH_BASE + nxt * B_STG;
    char* BLn = smem_c + BL_BASE + nxt * B_STG;
    uint32_t h01, l01, h23, l23;
    bsplit(a0r.x, a0r.y, h01, l01);
    bsplit(a0r.z, a0r.w, h23, l23);
    *reinterpret_cast<uint4*>(An + a_st0) = make_uint4(h01, l01, h23, l23);
    bsplit(a1r.x, a1r.y, h01, l01);
    bsplit(a1r.z, a1r.w, h23, l23);
    *reinterpret_cast<uint4*>(An + a_st1) = make_uint4(h01, l01, h23, l23);
#pragma unroll
    for (int i = 0; i < 4; i++) {
        bsplit(b4r[i].x, b4r[i].y, h01, l01);
        bsplit(b4r[i].z, b4r[i].w, h23, l23);
        *reinterpret_cast<uint2*>(BHn + b_st0 + i * 8 * 272) = make_uint2(h01, h23);
        *reinterpret_cast<uint2*>(BLn + b_st0 + i * 8 * 272) = make_uint2(l01, l23);
    }
}

__device__ __forceinline__ void bf16x3_gemm(const float* __restrict__ A,
                                            const float* __restrict__ W,
                                            float* __restrict__ C) {
    extern __shared__ char smem_c[];
    const uint32_t sb = smem_to_u32(smem_c);
    const int t    = threadIdx.x;
    const int warp = t >> 5;
    const int lane = t & 31;
    const int q    = lane >> 2;
    const int c4   = lane & 3;
    const int bm = blockIdx.y * 64;
    const int bn = blockIdx.x * 128;
    const int wm = (warp >> 2) * 32;   // 0 or 32
    const int wn = (warp & 3) * 32;    // 0,32,64,96

    // A staging: 64 rows x 32 k = 512 float4; each thread 2 (rows t>>3, 32+(t>>3))
    const int ar = t >> 3;             // 0..31
    const int akg = (t & 7) * 4;       // k group
    const float* Ag = A + (size_t)(bm + ar) * DIMc + akg;
    const uint32_t a_st0 = (uint32_t)(ar * 160 + (t & 7) * 16);
    const uint32_t a_st1 = a_st0 + 32 * 160;
    // B staging: 32 krows x 128 n = 1024 float4; each thread 4 (krows t>>5 + 8i)
    const int bkr = t >> 5;            // 0..7
    const int bnc = (t & 31) * 4;
    const float* Bg = W + (size_t)bkr * DIMc + bn + bnc;
    const uint32_t b_st0 = (uint32_t)(bkr * 272 + (t & 31) * 8);

    float acc[2][4][4];
#pragma unroll
    for (int i = 0; i < 2; i++)
#pragma unroll
        for (int j = 0; j < 4; j++)
#pragma unroll
            for (int e = 0; e < 4; e++) acc[i][j][e] = 0.f;

    // prologue: stage 0
    float4 a0r = *reinterpret_cast<const float4*>(Ag);
    float4 a1r = *reinterpret_cast<const float4*>(Ag + 32 * DIMc);
    float4 b4r[4];
#pragma unroll
    for (int i = 0; i < 4; i++)
        b4r[i] = *reinterpret_cast<const float4*>(Bg + (size_t)(8 * i) * DIMc);
    stage_store(smem_c, 0, a_st0, a_st1, b_st0, a0r, a1r, b4r);
    __syncthreads();

#pragma unroll 1
    for (int s = 0; s < 8; s++) {
        const int cur = s & 1;
        if (s < 7) {
            const int k0 = (s + 1) * 32;
            a0r = *reinterpret_cast<const float4*>(Ag + k0);
            a1r = *reinterpret_cast<const float4*>(Ag + 32 * DIMc + k0);
#pragma unroll
            for (int i = 0; i < 4; i++)
                b4r[i] = *reinterpret_cast<const float4*>(
                    Bg + (size_t)(k0 + 8 * i) * DIMc);
        }

        const char* Ab = smem_c + cur * A_STG;
        const uint32_t bhb = sb + BH_BASE + cur * B_STG;
        const uint32_t blb = sb + BL_BASE + cur * B_STG;

#pragma unroll
        for (int k16 = 0; k16 < 2; k16++) {
            uint32_t ah[2][4], al[2][4];
#pragma unroll
            for (int mt = 0; mt < 2; mt++) {
                const uint2* Ap = reinterpret_cast<const uint2*>(Ab)
                                + (wm + mt * 16 + q) * 20 + k16 * 8 + c4;
                uint2 u0 = Ap[0];
                uint2 u1 = Ap[160];
                uint2 u2 = Ap[4];
                uint2 u3 = Ap[164];
                ah[mt][0] = u0.x; al[mt][0] = u0.y;
                ah[mt][1] = u1.x; al[mt][1] = u1.y;
                ah[mt][2] = u2.x; al[mt][2] = u2.y;
                ah[mt][3] = u3.x; al[mt][3] = u3.y;
            }
            uint32_t bh[2][4], bl[2][4];
#pragma unroll
            for (int nc = 0; nc < 2; nc++) {
                uint32_t off = (uint32_t)((k16 * 16 + (lane & 15)) * 272
                              + (wn + nc * 16 + ((lane >> 4) << 3)) * 2);
                ldsm_x4_t(bh[nc], bhb + off);
                ldsm_x4_t(bl[nc], blb + off);
            }
#pragma unroll
            for (int mt = 0; mt < 2; mt++)
#pragma unroll
                for (int n8 = 0; n8 < 4; n8++) {
                    const int nc = n8 >> 1, jj = (n8 & 1) * 2;
                    mma_bf16(acc[mt][n8], ah[mt], bh[nc][jj], bh[nc][jj + 1]);
                    mma_bf16(acc[mt][n8], ah[mt], bl[nc][jj], bl[nc][jj + 1]);
                    mma_bf16(acc[mt][n8], al[mt], bh[nc][jj], bh[nc][jj + 1]);
                }
        }

        if (s < 7) {
            __syncthreads();   // MMA reads done before overwrite (2-buffer rotation)
            stage_store(smem_c, cur ^ 1, a_st0, a_st1, b_st0, a0r, a1r, b4r);
            __syncthreads();
        }
    }

    // epilogue
#pragma unroll
    for (int mt = 0; mt < 2; mt++) {
#pragma unroll
        for (int n8 = 0; n8 < 4; n8++) {
            const int gr0 = bm + wm + mt * 16 + q;
            const int gc  = bn + wn + n8 * 8 + 2 * c4;
            *reinterpret_cast<float2*>(C + (size_t)gr0 * DIMc + gc) =
                make_float2(acc[mt][n8][0], acc[mt][n8][1]);
            *reinterpret_cast<float2*>(C + (size_t)(gr0 + 8) * DIMc + gc) =
                make_float2(acc[mt][n8][2], acc[mt][n8][3]);
        }
    }
}

__global__ void __launch_bounds__(256, 2)
gemm_qkv(const float* __restrict__ X,
         const float* __restrict__ Wq, const float* __restrict__ Wk,
         const float* __restrict__ Wv) {
    const float* W = (blockIdx.z == 0) ? Wq : (blockIdx.z == 1) ? Wk : Wv;
    float* C = (blockIdx.z == 0) ? g_q : (blockIdx.z == 1) ? g_k : g_v;
    bf16x3_gemm(X, W, C);
}

__global__ void __launch_bounds__(256, 2)
gemm_proj(const float* __restrict__ W, float* __restrict__ out) {
    bf16x3_gemm(g_h, W, out);
}

// ---------------------------------------------------------------------------
// Attention: block per token, warp per head, lane = dim.
// ---------------------------------------------------------------------------
__global__ void __launch_bounds__(256, 6)
attn_kernel(const float* __restrict__ mo) {
    const int r = blockIdx.x;
    const int b = (r >= Nn) ? 1 : 0;
    const int warp = threadIdx.x >> 5;
    const int lane = threadIdx.x & 31;

    float ox = mo[(size_t)r * 2 + 0];
    float oy = mo[(size_t)r * 2 + 1];
    ox = fminf(fmaxf(ox, 1.0f), (float)(Ww - 2) - 0.001f);
    oy = fminf(fmaxf(oy, 1.0f), (float)(Hh - 2) - 0.001f);
    const float mx = floorf(ox), my = floorf(oy);
    const float fx = ox - mx,   fy = oy - my;

    const int ibase = b * Nn + ((int)my - 1) * Ww + ((int)mx - 1);

    const size_t head_off = (size_t)warp * HDc + lane;
    const float qd = g_q[(size_t)r * DIMc + head_off] * SCALEF;

    float part[16];
#pragma unroll
    for (int a = 0; a < 16; a++) {
        int ia = ibase + (a >> 2) * Ww + (a & 3);
        part[a] = qd * g_k[(size_t)ia * DIMc + head_off];
    }

    // Multi-value butterfly: 16 dots reduced in 16+ shuffles.
    float v8[8];
    {
        const bool hi = (lane & 16) != 0;
#pragma unroll
        for (int j = 0; j < 8; j++) {
            float send = hi ? part[j] : part[j + 8];
            float keep = hi ? part[j + 8] : part[j];
            v8[j] = keep + __shfl_xor_sync(0xffffffffu, send, 16);
        }
    }
    float v4[4];
    {
        const bool hi = (lane & 8) != 0;
#pragma unroll
        for (int j = 0; j < 4; j++) {
            float send = hi ? v8[j] : v8[j + 4];
            float keep = hi ? v8[j + 4] : v8[j];
            v4[j] = keep + __shfl_xor_sync(0xffffffffu, send, 8);
        }
    }
    float v2[2];
    {
        const bool hi = (lane & 4) != 0;
        float s0 = hi ? v4[2] : v4[0];
        float s1 = hi ? v4[3] : v4[1];
        float d0 = hi ? v4[0] : v4[2];
        float d1 = hi ? v4[1] : v4[3];
        v2[0] = s0 + __shfl_xor_sync(0xffffffffu, d0, 4);
        v2[1] = s1 + __shfl_xor_sync(0xffffffffu, d1, 4);
    }
    float v1;
    {
        const bool hi = (lane & 2) != 0;
        float keep = hi ? v2[1] : v2[0];
        float send = hi ? v2[0] : v2[1];
        v1 = keep + __shfl_xor_sync(0xffffffffu, send, 2);
    }
    float sfin = v1 + __shfl_xor_sync(0xffffffffu, v1, 1);
    float sa = __shfl_sync(0xffffffffu, sfin, (lane & 15) * 2);

    const int axp = lane & 3;
    const int ayp = (lane >> 2) & 3;
    const float wxv = (axp == 0) ? (1.f - fx) : ((axp == 3) ? fx : 1.f);
    const float wyv = (ayp == 0) ? (1.f - fy) : ((ayp == 3) ? fy : 1.f);
    const float bw = wxv * wyv;

    float mval = sa;
#pragma unroll
    for (int o = 8; o > 0; o >>= 1)
        mval = fmaxf(mval, __shfl_xor_sync(0xffffffffu, mval, o));
    float e = (lane < 16) ? __expf(sa - mval) * bw : 0.f;
    float se = e;
#pragma unroll
    for (int o = 16; o > 0; o >>= 1)
        se += __shfl_xor_sync(0xffffffffu, se, o);
    const float p = __fdividef(e, se);

    float accv = 0.f;
#pragma unroll
    for (int a = 0; a < 16; a++) {
        int ia = ibase + (a >> 2) * Ww + (a & 3);
        float va = g_v[(size_t)ia * DIMc + head_off];
        float pa = __shfl_sync(0xffffffffu, p, a);
        accv += pa * va;
    }
    g_h[(size_t)r * DIMc + head_off] = accv;
}

// ---------------------------------------------------------------------------
extern "C" void kernel_launch(void* const* d_in, const int* in_sizes, int n_in,
                              void* d_out, int out_size) {
    const float* x  = (const float*)d_in[0];
    const float* mo = (const float*)d_in[1];
    const float* Wq = (const float*)d_in[2];
    const float* Wk = (const float*)d_in[3];
    const float* Wv = (const float*)d_in[4];
    const float* Wp = (const float*)d_in[5];
    float* out = (float*)d_out;

    cudaFuncSetAttribute(gemm_qkv, cudaFuncAttributeMaxDynamicSharedMemorySize, SMEM_GEMM);
    cudaFuncSetAttribute(gemm_proj, cudaFuncAttributeMaxDynamicSharedMemorySize, SMEM_GEMM);

    dim3 gqkv(2, Mrows / 64, 3);    // (2, 320, 3)
    gemm_qkv<<<gqkv, 256, SMEM_GEMM>>>(x, Wq, Wk, Wv);
    attn_kernel<<<Mrows, 256>>>(mo);
    dim3 gp(2, Mrows / 64);         // (2, 320)
    gemm_proj<<<gp, 256, SMEM_GEMM>>>(Wp, out);
}